// round 11
// baseline (speedup 1.0000x reference)
#include <cuda_runtime.h>
#include <cstdint>

// IntraLoss: loss = (1/N) * sum_n || features[n] - center[labels[n]] ||_2
// N=32768, C=1000, D=512. features f32 [N,D], labels int32 [N], center f32 [C,D].
//
// 2048 blocks x 256 threads (8 warps). Block owns 16 contiguous rows (32KB).
// All 4 chunks (8KB = 4 rows each) are fetched via cp.async.bulk at t=0 into
// 4 distinct SMEM buffers with independent mbarriers (no ring reuse, no
// inter-stage barriers). Warp w consumes rows {2w, 2w+1} (chunk w/2):
// features from SMEM (LDS), centers via LDG (L2-hot). This removes the
// 64MB feature stream from the L1tex wavefront path. Last block folds
// the 2048 partials.

#define NROWS 32768
#define NCLS  1000
#define DDIM  512
#define ROWS_PER_BLK 16
#define NBLK  (NROWS / ROWS_PER_BLK)              // 2048
#define NCHUNK 4
#define ROWS_PER_CHUNK 4
#define CHUNK_BYTES (ROWS_PER_CHUNK * DDIM * 4)   // 8192
#define ROW_BYTES (DDIM * 4)                      // 2048

__device__ float g_partials[NBLK];
__device__ unsigned int g_counter = 0;

__device__ __forceinline__ uint32_t s2u(const void* p) {
    return (uint32_t)__cvta_generic_to_shared(p);
}
__device__ __forceinline__ void mbar_init(uint32_t mbar, uint32_t count) {
    asm volatile("mbarrier.init.shared.b64 [%0], %1;" :: "r"(mbar), "r"(count) : "memory");
}
__device__ __forceinline__ void mbar_expect_tx(uint32_t mbar, uint32_t bytes) {
    asm volatile("mbarrier.arrive.expect_tx.shared.b64 _, [%0], %1;"
                 :: "r"(mbar), "r"(bytes) : "memory");
}
__device__ __forceinline__ void bulk_copy_g2s(uint32_t dst, const void* src,
                                              uint32_t bytes, uint32_t mbar) {
    asm volatile(
        "cp.async.bulk.shared::cta.global.mbarrier::complete_tx::bytes [%0], [%1], %2, [%3];"
        :: "r"(dst), "l"(src), "r"(bytes), "r"(mbar) : "memory");
}
__device__ __forceinline__ void mbar_wait0(uint32_t mbar) {
    asm volatile(
        "{\n\t.reg .pred P;\n\t"
        "W_%=: mbarrier.try_wait.parity.acquire.cta.shared::cta.b64 P, [%0], 0, 0x989680;\n\t"
        "@P bra.uni D_%=;\n\t"
        "bra.uni W_%=;\n\t"
        "D_%=:\n\t}"
        :: "r"(mbar) : "memory");
}

__global__ __launch_bounds__(256) void intra_loss_kernel(
    const float* __restrict__ feats,     // [N, D]
    const int* __restrict__ labels,      // [N]
    const float4* __restrict__ center,   // [C, D/4]
    float* __restrict__ out)
{
    __shared__ alignas(128) char sbuf[NCHUNK][CHUNK_BYTES];   // 32 KB
    __shared__ alignas(8) unsigned long long mbar_store[NCHUNK];
    __shared__ float wpart[8];
    __shared__ bool is_last;

    const int tid  = threadIdx.x;
    const int lane = tid & 31;
    const int w    = tid >> 5;                    // warp 0..7
    const int base = blockIdx.x * ROWS_PER_BLK;

    if (tid == 0) {
        #pragma unroll
        for (int c = 0; c < NCHUNK; c++) mbar_init(s2u(&mbar_store[c]), 1);
    }
    __syncthreads();

    // Issue all 4 bulk copies immediately (async engine, bypasses L1tex).
    if (tid == 0) {
        #pragma unroll
        for (int c = 0; c < NCHUNK; c++) {
            uint32_t mb = s2u(&mbar_store[c]);
            mbar_expect_tx(mb, CHUNK_BYTES);
            bulk_copy_g2s(s2u(&sbuf[c][0]),
                          feats + (size_t)(base + c * ROWS_PER_CHUNK) * DDIM,
                          CHUNK_BYTES, mb);
        }
    }

    // Warp w handles rows base+2w and base+2w+1 (both in chunk w/2).
    const int r0 = 2 * w;
    const int r1 = 2 * w + 1;
    int lbl0 = __ldg(&labels[base + r0]);
    int lbl1 = __ldg(&labels[base + r1]);
    lbl0 = min(max(lbl0, 0), NCLS - 1);
    lbl1 = min(max(lbl1, 0), NCLS - 1);

    const float4* cr0 = center + (size_t)lbl0 * (DDIM / 4) + lane;
    const float4* cr1 = center + (size_t)lbl1 * (DDIM / 4) + lane;

    mbar_wait0(s2u(&mbar_store[w >> 1]));

    const float4* s0 = (const float4*)(&sbuf[w >> 1][(r0 & 3) * ROW_BYTES]) + lane;
    const float4* s1 = (const float4*)(&sbuf[w >> 1][(r1 & 3) * ROW_BYTES]) + lane;

    float acc0 = 0.0f, acc1 = 0.0f;
    #pragma unroll
    for (int i = 0; i < 4; i++) {
        float4 a0 = s0[32 * i];
        float4 b0 = __ldg(cr0 + 32 * i);
        float4 a1 = s1[32 * i];
        float4 b1 = __ldg(cr1 + 32 * i);
        float d;
        d = a0.x - b0.x; acc0 = fmaf(d, d, acc0);
        d = a0.y - b0.y; acc0 = fmaf(d, d, acc0);
        d = a0.z - b0.z; acc0 = fmaf(d, d, acc0);
        d = a0.w - b0.w; acc0 = fmaf(d, d, acc0);
        d = a1.x - b1.x; acc1 = fmaf(d, d, acc1);
        d = a1.y - b1.y; acc1 = fmaf(d, d, acc1);
        d = a1.z - b1.z; acc1 = fmaf(d, d, acc1);
        d = a1.w - b1.w; acc1 = fmaf(d, d, acc1);
    }

    #pragma unroll
    for (int sh = 16; sh > 0; sh >>= 1) {
        acc0 += __shfl_xor_sync(0xffffffffu, acc0, sh);
        acc1 += __shfl_xor_sync(0xffffffffu, acc1, sh);
    }

    if (lane == 0) wpart[w] = sqrtf(acc0) + sqrtf(acc1);
    __syncthreads();

    if (tid == 0) {
        float s = 0.0f;
        #pragma unroll
        for (int i = 0; i < 8; i++) s += wpart[i];
        g_partials[blockIdx.x] = s;
        __threadfence();
        unsigned int old = atomicAdd(&g_counter, 1u);
        is_last = (old == NBLK - 1);
    }
    __syncthreads();

    if (is_last) {
        float v = 0.0f;
        #pragma unroll
        for (int i = 0; i < NBLK / 256; i++)      // 8 each
            v += g_partials[tid + i * 256];

        #pragma unroll
        for (int sh = 16; sh > 0; sh >>= 1)
            v += __shfl_xor_sync(0xffffffffu, v, sh);

        if (lane == 0) wpart[w] = v;
        __syncthreads();

        if (tid == 0) {
            float t = 0.0f;
            #pragma unroll
            for (int i = 0; i < 8; i++) t += wpart[i];
            out[0] = t * (1.0f / (float)NROWS);
            g_counter = 0;   // reset for next graph replay
        }
    }
}

extern "C" void kernel_launch(void* const* d_in, const int* in_sizes, int n_in,
                              void* d_out, int out_size)
{
    const float* feats   = (const float*)d_in[0];
    const int* labels    = (const int*)d_in[1];
    const float4* center = (const float4*)d_in[2];
    float* out           = (float*)d_out;

    intra_loss_kernel<<<NBLK, 256>>>(feats, labels, center, out);
}

// round 12
// speedup vs baseline: 1.3145x; 1.3145x over previous
#include <cuda_runtime.h>

// IntraLoss: loss = (1/N) * sum_n || features[n] - center[labels[n]] ||_2
// N=32768, C=1000, D=512. features f32 [N,D], labels int32 [N], center f32 [C,D].
//
// R4 structure (best known): 1024 blocks x 256 threads, 8 warps x 4 rows,
// 8 lanes/row, single wave, last-block reduction. Changes vs R4:
//  - features loaded with __ldcg (L2-only, no L1 allocate) so the 64MB
//    stream stops evicting the 2MB center working set from L1
//  - dual accumulators (halved FMA dependency chain)

#define NROWS 32768
#define NCLS  1000
#define DDIM  512
#define NBLK  1024

__device__ float g_partials[NBLK];
__device__ unsigned int g_counter = 0;

__global__ __launch_bounds__(256) void intra_loss_kernel(
    const float4* __restrict__ feats,    // [N, D/4]
    const int* __restrict__ labels,      // [N] int32
    const float4* __restrict__ center,   // [C, D/4]
    float* __restrict__ out)
{
    const int lane  = threadIdx.x & 31;
    const int wib   = threadIdx.x >> 5;                      // 0..7
    const int warpG = (blockIdx.x << 3) + wib;               // 0..8191
    const int g     = lane >> 3;                             // group 0..3
    const int l     = lane & 7;                              // lane in group
    const int row   = (warpG << 2) + g;                      // 4 rows per warp

    int lbl = labels[row];
    lbl = min(max(lbl, 0), NCLS - 1);

    const float4* fr = feats  + (size_t)row * (DDIM / 4) + l;
    const float4* cr = center + (size_t)lbl * (DDIM / 4) + l;

    float acc0 = 0.0f, acc1 = 0.0f;
    #pragma unroll
    for (int i = 0; i < 16; i++) {
        float4 a = __ldcg(fr + i * 8);     // L2-only: don't pollute L1
        float4 b = __ldg(cr + i * 8);      // cached: center stays L1-warm
        float dx = a.x - b.x;
        float dy = a.y - b.y;
        float dz = a.z - b.z;
        float dw = a.w - b.w;
        acc0 = fmaf(dx, dx, acc0);
        acc1 = fmaf(dy, dy, acc1);
        acc0 = fmaf(dz, dz, acc0);
        acc1 = fmaf(dw, dw, acc1);
    }
    float acc = acc0 + acc1;

    // reduce within 8-lane group (all 4 rows in parallel)
    acc += __shfl_xor_sync(0xffffffffu, acc, 1);
    acc += __shfl_xor_sync(0xffffffffu, acc, 2);
    acc += __shfl_xor_sync(0xffffffffu, acc, 4);

    // one sqrt per row (group leaders), zeros elsewhere
    float d = (l == 0) ? sqrtf(acc) : 0.0f;

    // sum the 4 row-distances across groups
    d += __shfl_xor_sync(0xffffffffu, d, 8);
    d += __shfl_xor_sync(0xffffffffu, d, 16);

    __shared__ float smem[8];
    __shared__ bool is_last;
    if (lane == 0) smem[wib] = d;
    __syncthreads();

    if (threadIdx.x == 0) {
        float s = 0.0f;
        #pragma unroll
        for (int i = 0; i < 8; i++) s += smem[i];
        g_partials[blockIdx.x] = s;
        __threadfence();
        unsigned int old = atomicAdd(&g_counter, 1u);
        is_last = (old == NBLK - 1);
    }
    __syncthreads();

    if (is_last) {
        float v = 0.0f;
        #pragma unroll
        for (int i = 0; i < 4; i++)
            v += g_partials[threadIdx.x + i * 256];

        #pragma unroll
        for (int s = 16; s > 0; s >>= 1)
            v += __shfl_xor_sync(0xffffffffu, v, s);

        __shared__ float smem2[8];
        if (lane == 0) smem2[wib] = v;
        __syncthreads();

        if (threadIdx.x == 0) {
            float w = 0.0f;
            #pragma unroll
            for (int i = 0; i < 8; i++) w += smem2[i];
            out[0] = w * (1.0f / (float)NROWS);
            g_counter = 0;   // reset for next graph replay
        }
    }
}

extern "C" void kernel_launch(void* const* d_in, const int* in_sizes, int n_in,
                              void* d_out, int out_size)
{
    const float4* feats  = (const float4*)d_in[0];
    const int* labels    = (const int*)d_in[1];
    const float4* center = (const float4*)d_in[2];
    float* out           = (float*)d_out;

    intra_loss_kernel<<<NBLK, 256>>>(feats, labels, center, out);
}